// round 4
// baseline (speedup 1.0000x reference)
#include <cuda_runtime.h>
#include <cstdint>

#define BATCH 256
#define CH    2048
#define HW    196
#define NEXP  16
#define NA    3000
#define KDIM  2048

#define MT    16          // batches per tile
#define PT    20          // att_t pitch (conflict-free: odd multiple of 4)
#define MAXTILES 32
#define ABLK  64          // a-rows per work item
#define NABLK 47          // ceil(3000/64)
#define GT    512         // gemm threads (16 warps, 4 rows each)

__device__ float g_attended[BATCH * CH];
__device__ int   g_perm[BATCH];
__device__ int   g_tile_e[MAXTILES];
__device__ int   g_tile_m0[MAXTILES];
__device__ int   g_tile_cnt[MAXTILES];
__device__ int   g_numtiles;
__device__ int   g_ctr;
__device__ __align__(16) float g_stage[MAXTILES][KDIM][PT];  // 5.2 MB, L2-resident

// ---- packed f32x2 helpers (sm_103a) ---------------------------------------
__device__ __forceinline__ unsigned long long fma2(unsigned long long a,
                                                   unsigned long long b,
                                                   unsigned long long c) {
    unsigned long long d;
    asm("fma.rn.f32x2 %0, %1, %2, %3;" : "=l"(d) : "l"(a), "l"(b), "l"(c));
    return d;
}
__device__ __forceinline__ unsigned long long add2(unsigned long long a,
                                                   unsigned long long b) {
    unsigned long long d;
    asm("add.rn.f32x2 %0, %1, %2;" : "=l"(d) : "l"(a), "l"(b));
    return d;
}
__device__ __forceinline__ float2 unpack2(unsigned long long v) {
    float2 f;
    asm("mov.b64 {%0,%1}, %2;" : "=f"(f.x), "=f"(f.y) : "l"(v));
    return f;
}
__device__ __forceinline__ unsigned long long bcast2(float v) {
    unsigned long long d;
    asm("mov.b64 %0, {%1, %1};" : "=l"(d) : "f"(v));
    return d;
}
__device__ __forceinline__ void cp16(void* sdst, const void* gsrc) {
    uint32_t s = (uint32_t)__cvta_generic_to_shared(sdst);
    asm volatile("cp.async.cg.shared.global [%0], [%1], 16;\n" :: "r"(s), "l"(gsrc));
}
__device__ __forceinline__ void cp_commit() {
    asm volatile("cp.async.commit_group;\n" ::: "memory");
}
__device__ __forceinline__ void cp_wait0() {
    asm volatile("cp.async.wait_group 0;\n" ::: "memory");
}

// ---------------------------------------------------------------------------
// Kernel 1: masked weighted average pool (DRAM-bound, at floor).
// ---------------------------------------------------------------------------
__global__ void pool_kernel(const float* __restrict__ mask,
                            const float* __restrict__ feat) {
    int b   = blockIdx.x;
    int tid = threadIdx.x;
    int wid = tid >> 5, lane = tid & 31;

    __shared__ __align__(16) float m_s[HW];
    __shared__ float warp_sum[8];
    __shared__ float s_inv;

    float v = 0.f;
    if (tid < HW) {
        v = mask[b * HW + tid] + 1e-10f;
        m_s[tid] = v;
    }
    #pragma unroll
    for (int o = 16; o > 0; o >>= 1) v += __shfl_down_sync(0xffffffffu, v, o);
    if (lane == 0) warp_sum[wid] = v;
    __syncthreads();
    if (tid == 0) {
        float s = 0.f;
        #pragma unroll
        for (int i = 0; i < 8; i++) s += warp_sum[i];
        s_inv = 1.0f / s;
    }
    __syncthreads();
    float inv = s_inv;

    const float4* m4 = (const float4*)m_s;
    float4 mA = m4[lane];
    float4 mB = (lane < 17) ? m4[lane + 32] : make_float4(0.f, 0.f, 0.f, 0.f);

    int cbase = blockIdx.y * 256 + wid * 32;
    for (int it = 0; it < 32; it++) {
        int c = cbase + it;
        const float4* row = (const float4*)(feat + ((size_t)b * CH + c) * HW);
        float4 f = row[lane];
        float s = f.x * mA.x + f.y * mA.y + f.z * mA.z + f.w * mA.w;
        if (lane < 17) {
            float4 f2 = row[lane + 32];
            s += f2.x * mB.x + f2.y * mB.y + f2.z * mB.z + f2.w * mB.w;
        }
        #pragma unroll
        for (int o = 16; o > 0; o >>= 1) s += __shfl_down_sync(0xffffffffu, s, o);
        if (lane == 0) g_attended[b * CH + c] = s * inv;
    }
}

// ---------------------------------------------------------------------------
// Kernel 2: group batches by expert, build tiles of <=16, reset work counter.
// ---------------------------------------------------------------------------
__global__ void group_kernel(const void* __restrict__ inst) {
    int tid = threadIdx.x;
    __shared__ int odd_nz;
    __shared__ int sh_e[BATCH];
    __shared__ int cnt[NEXP];
    __shared__ int off[NEXP + 1];

    if (tid == 0) { odd_nz = 0; g_ctr = 0; }
    __syncthreads();
    const int* iv = (const int*)inst;
    if (tid < BATCH / 2 && iv[2 * tid + 1] != 0) atomicExch(&odd_nz, 1);
    __syncthreads();

    int e;
    if (odd_nz == 0) e = (int)((const long long*)inst)[tid];
    else             e = iv[tid];

    sh_e[tid] = e;
    if (tid < NEXP) cnt[tid] = 0;
    __syncthreads();

    atomicAdd(&cnt[e], 1);
    int rank = 0;
    for (int j = 0; j < tid; j++) rank += (sh_e[j] == e);
    __syncthreads();

    if (tid == 0) {
        off[0] = 0;
        for (int i = 0; i < NEXP; i++) off[i + 1] = off[i] + cnt[i];
        int nt = 0;
        for (int ei = 0; ei < NEXP; ei++)
            for (int s = 0; s < cnt[ei]; s += MT) {
                g_tile_e[nt]   = ei;
                g_tile_m0[nt]  = off[ei] + s;
                g_tile_cnt[nt] = min(MT, cnt[ei] - s);
                nt++;
            }
        g_numtiles = nt;
    }
    __syncthreads();
    g_perm[off[e] + rank] = tid;
}

// ---------------------------------------------------------------------------
// Kernel 3: stage transposed attended panels:
//   g_stage[tile][k][b] = g_attended[perm[m0+b]][k]
// ---------------------------------------------------------------------------
__global__ void stage_kernel() {
    int tile = blockIdx.y;
    if (tile >= g_numtiles) return;
    int k0 = blockIdx.x * 256;
    int tid = threadIdx.x;

    __shared__ float s[MT][256 + 4];
    __shared__ int s_bb[MT];
    if (tid < MT) {
        int m0 = g_tile_m0[tile], mcnt = g_tile_cnt[tile];
        s_bb[tid] = g_perm[m0 + min(tid, mcnt - 1)];
    }
    __syncthreads();

    int b = tid >> 4, f = tid & 15;
    const float* src = g_attended + (size_t)s_bb[b] * KDIM + k0;
    #pragma unroll
    for (int j = 0; j < 4; j++) {
        float4 v = *(const float4*)(src + (f + 16 * j) * 4);
        *(float4*)&s[b][(f + 16 * j) * 4] = v;
    }
    __syncthreads();

    int k = tid;
    float o[PT];
    #pragma unroll
    for (int bi = 0; bi < MT; bi++) o[bi] = s[bi][k];
    #pragma unroll
    for (int bi = MT; bi < PT; bi++) o[bi] = 0.f;
    float* dst = &g_stage[tile][k0 + k][0];
    #pragma unroll
    for (int q = 0; q < PT / 4; q++)
        *(float4*)(dst + q * 4) = *(float4*)&o[q * 4];
}

// ---------------------------------------------------------------------------
// Kernel 4: persistent grouped GEMM.
// Item = (tile, a-block of 64). 512 thr / 16 warps; warp owns 4 a-rows.
// att panel fully resident in smem (160KB); W streams gmem->regs with
// 2-chunk prefetch ring; FFMA2 over packed b-pairs; no syncs in hot loop.
// ---------------------------------------------------------------------------
__global__ __launch_bounds__(GT, 1)
void gemm_kernel(const float* __restrict__ W,
                 const float* __restrict__ bias,
                 float* __restrict__ out) {
    extern __shared__ __align__(16) float att[];     // [KDIM][PT]
    __shared__ int s_item;
    __shared__ int s_bb[MT];
    __shared__ int s_e, s_mcnt;

    int tid = threadIdx.x;
    int wid = tid >> 5, lane = tid & 31;
    int cur_tile = -1;
    int numitems = g_numtiles * NABLK;

    for (;;) {
        if (tid == 0) s_item = atomicAdd(&g_ctr, 1);
        __syncthreads();                    // also fences prior epilogue reads
        int item = s_item;
        if (item >= numitems) break;
        int tile = item / NABLK;
        int ab   = item - tile * NABLK;

        if (tile != cur_tile) {
            if (tid == 0) { s_e = g_tile_e[tile]; s_mcnt = g_tile_cnt[tile]; }
            if (tid < MT)
                s_bb[tid] = g_perm[g_tile_m0[tile] + min(tid, g_tile_cnt[tile] - 1)];
            const float4* src = (const float4*)&g_stage[tile][0][0];
            float4* dst = (float4*)att;
            #pragma unroll
            for (int i = 0; i < KDIM * PT / 4 / GT; i++)
                cp16(dst + tid + i * GT, src + tid + i * GT);
            cp_commit(); cp_wait0();
            __syncthreads();
            cur_tile = tile;
        }

        int e = s_e, mcnt = s_mcnt;
        int a0 = ab * ABLK;

        const float* wr0; const float* wr1; const float* wr2; const float* wr3;
        {
            int a = a0 + wid * 4;
            int c0 = min(a,     NA - 1), c1 = min(a + 1, NA - 1);
            int c2 = min(a + 2, NA - 1), c3 = min(a + 3, NA - 1);
            wr0 = W + ((size_t)e * NA + c0) * KDIM;
            wr1 = W + ((size_t)e * NA + c1) * KDIM;
            wr2 = W + ((size_t)e * NA + c2) * KDIM;
            wr3 = W + ((size_t)e * NA + c3) * KDIM;
        }

        unsigned long long acc[4][8];
        #pragma unroll
        for (int r = 0; r < 4; r++)
            #pragma unroll
            for (int p = 0; p < 8; p++) acc[r][p] = 0ull;

        float w0[4], w1[4];
        w0[0] = wr0[lane];      w0[1] = wr1[lane];
        w0[2] = wr2[lane];      w0[3] = wr3[lane];
        w1[0] = wr0[32 + lane]; w1[1] = wr1[32 + lane];
        w1[2] = wr2[32 + lane]; w1[3] = wr3[32 + lane];

        const float* tbase = att + lane * PT;

        #pragma unroll 4
        for (int c = 0; c < KDIM / 32; c++) {
            int kn = ((c + 2) * 32 + lane) & (KDIM - 1);   // wrap: harmless dup
            float w2[4];
            w2[0] = wr0[kn]; w2[1] = wr1[kn]; w2[2] = wr2[kn]; w2[3] = wr3[kn];

            const float* tp = tbase + c * 32 * PT;
            ulonglong2 tA = *(const ulonglong2*)(tp);
            ulonglong2 tB = *(const ulonglong2*)(tp + 4);
            ulonglong2 tC = *(const ulonglong2*)(tp + 8);
            ulonglong2 tD = *(const ulonglong2*)(tp + 12);

            #pragma unroll
            for (int r = 0; r < 4; r++) {
                unsigned long long wp = bcast2(w0[r]);
                acc[r][0] = fma2(wp, tA.x, acc[r][0]);
                acc[r][1] = fma2(wp, tA.y, acc[r][1]);
                acc[r][2] = fma2(wp, tB.x, acc[r][2]);
                acc[r][3] = fma2(wp, tB.y, acc[r][3]);
                acc[r][4] = fma2(wp, tC.x, acc[r][4]);
                acc[r][5] = fma2(wp, tC.y, acc[r][5]);
                acc[r][6] = fma2(wp, tD.x, acc[r][6]);
                acc[r][7] = fma2(wp, tD.y, acc[r][7]);
            }
            #pragma unroll
            for (int r = 0; r < 4; r++) { w0[r] = w1[r]; w1[r] = w2[r]; }
        }

        // epilogue: packed butterfly reduce, single-lane scatter
        #pragma unroll
        for (int r = 0; r < 4; r++) {
            #pragma unroll
            for (int p = 0; p < 8; p++) {
                unsigned long long v = acc[r][p];
                #pragma unroll
                for (int o = 16; o > 0; o >>= 1)
                    v = add2(v, __shfl_xor_sync(0xffffffffu, v, o));
                if (lane == r * 8 + p) {
                    float2 f = unpack2(v);
                    int a = a0 + wid * 4 + r;
                    if (a < NA) {
                        float bb_ = bias[e * NA + a];
                        int b0 = 2 * p, b1 = 2 * p + 1;
                        if (b0 < mcnt) out[(size_t)s_bb[b0] * NA + a] = f.x + bb_;
                        if (b1 < mcnt) out[(size_t)s_bb[b1] * NA + a] = f.y + bb_;
                    }
                }
            }
        }
    }
}

// ---------------------------------------------------------------------------
extern "C" void kernel_launch(void* const* d_in, const int* in_sizes, int n_in,
                              void* d_out, int out_size) {
    const float* mask = (const float*)d_in[0];
    const float* feat = (const float*)d_in[1];
    const float* W    = (const float*)d_in[2];
    const float* bias = (const float*)d_in[3];
    const void*  inst = d_in[4];
    float* out = (float*)d_out;

    const int GEMM_SMEM = KDIM * PT * 4;   // 163840 B
    cudaFuncSetAttribute(gemm_kernel,
                         cudaFuncAttributeMaxDynamicSharedMemorySize, GEMM_SMEM);

    pool_kernel<<<dim3(BATCH, 8), 256>>>(mask, feat);
    group_kernel<<<1, BATCH>>>(inst);
    stage_kernel<<<dim3(KDIM / 256, MAXTILES), 256>>>();
    gemm_kernel<<<160, GT, GEMM_SMEM>>>(W, bias, out);
}

// round 6
// speedup vs baseline: 1.1383x; 1.1383x over previous
#include <cuda_runtime.h>
#include <cstdint>

#define BATCH 256
#define CH    2048
#define HW    196
#define NEXP  16
#define NA    3000
#define KDIM  2048

#define MT       24          // batches per expert tile (N)
#define MAXTILES 32
#define AB       128         // a-rows per CTA (M)
#define NABLK    24          // ceil(3000/128)
#define KC       128         // k-chunk (floats)
#define NCH      (KDIM/KC)   // 16 chunks
#define BP       24          // B pitch (floats) — conflict-free

__device__ float g_attended[BATCH * CH];
__device__ int   g_perm[BATCH];
__device__ int   g_tile_e[MAXTILES];
__device__ int   g_tile_m0[MAXTILES];
__device__ int   g_tile_cnt[MAXTILES];
__device__ int   g_numtiles;
__device__ __align__(16) float g_stage_hi[MAXTILES][KDIM][BP];  // 6.3 MB
__device__ __align__(16) float g_stage_lo[MAXTILES][KDIM][BP];  // 6.3 MB

// ---------------- helpers ----------------
__device__ __forceinline__ uint32_t to_tf32(float x) {
    uint32_t r;
    asm("cvt.rna.tf32.f32 %0, %1;" : "=r"(r) : "f"(x));
    return r;
}
__device__ __forceinline__ void mma8(float c[4], const uint32_t a[4],
                                     uint32_t b0, uint32_t b1) {
    asm volatile(
        "mma.sync.aligned.m16n8k8.row.col.f32.tf32.tf32.f32 "
        "{%0,%1,%2,%3}, {%4,%5,%6,%7}, {%8,%9}, {%0,%1,%2,%3};"
        : "+f"(c[0]), "+f"(c[1]), "+f"(c[2]), "+f"(c[3])
        : "r"(a[0]), "r"(a[1]), "r"(a[2]), "r"(a[3]), "r"(b0), "r"(b1));
}
__device__ __forceinline__ void cp16(void* sdst, const void* g) {
    uint32_t s = (uint32_t)__cvta_generic_to_shared(sdst);
    asm volatile("cp.async.cg.shared.global [%0], [%1], 16;" :: "r"(s), "l"(g));
}
__device__ __forceinline__ void cp_commit() {
    asm volatile("cp.async.commit_group;" ::: "memory");
}
__device__ __forceinline__ void cp_wait1() {
    asm volatile("cp.async.wait_group 1;" ::: "memory");
}

// ---------------------------------------------------------------------------
// Kernel 1: masked weighted average pool (DRAM-bound, at floor).
// ---------------------------------------------------------------------------
__global__ void pool_kernel(const float* __restrict__ mask,
                            const float* __restrict__ feat) {
    int b   = blockIdx.x;
    int tid = threadIdx.x;
    int wid = tid >> 5, lane = tid & 31;

    __shared__ __align__(16) float m_s[HW];
    __shared__ float warp_sum[8];
    __shared__ float s_inv;

    float v = 0.f;
    if (tid < HW) {
        v = mask[b * HW + tid] + 1e-10f;
        m_s[tid] = v;
    }
    #pragma unroll
    for (int o = 16; o > 0; o >>= 1) v += __shfl_down_sync(0xffffffffu, v, o);
    if (lane == 0) warp_sum[wid] = v;
    __syncthreads();
    if (tid == 0) {
        float s = 0.f;
        #pragma unroll
        for (int i = 0; i < 8; i++) s += warp_sum[i];
        s_inv = 1.0f / s;
    }
    __syncthreads();
    float inv = s_inv;

    const float4* m4 = (const float4*)m_s;
    float4 mA = m4[lane];
    float4 mB = (lane < 17) ? m4[lane + 32] : make_float4(0.f, 0.f, 0.f, 0.f);

    int cbase = blockIdx.y * 256 + wid * 32;
    for (int it = 0; it < 32; it++) {
        int c = cbase + it;
        const float4* row = (const float4*)(feat + ((size_t)b * CH + c) * HW);
        float4 f = row[lane];
        float s = f.x * mA.x + f.y * mA.y + f.z * mA.z + f.w * mA.w;
        if (lane < 17) {
            float4 f2 = row[lane + 32];
            s += f2.x * mB.x + f2.y * mB.y + f2.z * mB.z + f2.w * mB.w;
        }
        #pragma unroll
        for (int o = 16; o > 0; o >>= 1) s += __shfl_down_sync(0xffffffffu, s, o);
        if (lane == 0) g_attended[b * CH + c] = s * inv;
    }
}

// ---------------------------------------------------------------------------
// Kernel 2: group batches by expert (stable), tiles of <=24.
// ---------------------------------------------------------------------------
__global__ void group_kernel(const void* __restrict__ inst) {
    int tid = threadIdx.x;
    __shared__ int odd_nz;
    __shared__ int sh_e[BATCH];
    __shared__ int cnt[NEXP];
    __shared__ int off[NEXP + 1];

    if (tid == 0) odd_nz = 0;
    __syncthreads();
    const int* iv = (const int*)inst;
    if (tid < BATCH / 2 && iv[2 * tid + 1] != 0) atomicExch(&odd_nz, 1);
    __syncthreads();

    int e;
    if (odd_nz == 0) e = (int)((const long long*)inst)[tid];
    else             e = iv[tid];

    sh_e[tid] = e;
    if (tid < NEXP) cnt[tid] = 0;
    __syncthreads();

    atomicAdd(&cnt[e], 1);
    int rank = 0;
    for (int j = 0; j < tid; j++) rank += (sh_e[j] == e);
    __syncthreads();

    if (tid == 0) {
        off[0] = 0;
        for (int i = 0; i < NEXP; i++) off[i + 1] = off[i] + cnt[i];
        int nt = 0;
        for (int ei = 0; ei < NEXP; ei++)
            for (int s = 0; s < cnt[ei]; s += MT) {
                g_tile_e[nt]   = ei;
                g_tile_m0[nt]  = off[ei] + s;
                g_tile_cnt[nt] = min(MT, cnt[ei] - s);
                nt++;
            }
        g_numtiles = nt;
    }
    __syncthreads();
    g_perm[off[e] + rank] = tid;
}

// ---------------------------------------------------------------------------
// Kernel 3: stage transposed + tf32 hi/lo split attended panels:
//   g_stage_hi[tile][k][n] = tf32(att[bb[n]][k]); lo = tf32(x - hi)
// grid (KDIM/KC, MAXTILES) x 128 threads.
// ---------------------------------------------------------------------------
__global__ void stage_kernel() {
    int tile = blockIdx.y;
    if (tile >= g_numtiles) return;
    int k0 = blockIdx.x * KC;
    int tid = threadIdx.x;

    __shared__ float s[MT][KC + 4];
    __shared__ int s_bb[MT];
    if (tid < MT) {
        int m0 = g_tile_m0[tile], mcnt = g_tile_cnt[tile];
        s_bb[tid] = g_perm[m0 + min(tid, mcnt - 1)];
    }
    __syncthreads();

    // load 24 rows x 128 floats, coalesced (768 float4 / 128 thr = 6 each)
    #pragma unroll
    for (int i = 0; i < 6; i++) {
        int f4 = tid + 128 * i;
        int r = f4 >> 5, c = f4 & 31;
        float4 v = *(const float4*)(g_attended + (size_t)s_bb[r] * KDIM + k0 + c * 4);
        *(float4*)&s[r][c * 4] = v;
    }
    __syncthreads();

    // thread = one k: gather 24 b, split hi/lo, contiguous 96B writes
    int k = tid;
    float ohi[BP], olo[BP];
    #pragma unroll
    for (int n = 0; n < MT; n++) {
        float x = s[n][k];
        float hi = __uint_as_float(to_tf32(x));
        ohi[n] = hi;
        olo[n] = __uint_as_float(to_tf32(x - hi));
    }
    float* dh = &g_stage_hi[tile][k0 + k][0];
    float* dl = &g_stage_lo[tile][k0 + k][0];
    #pragma unroll
    for (int q = 0; q < BP / 4; q++) {
        *(float4*)(dh + q * 4) = *(float4*)&ohi[q * 4];
        *(float4*)(dl + q * 4) = *(float4*)&olo[q * 4];
    }
}

// ---------------------------------------------------------------------------
// Kernel 4: grouped GEMM via mma.sync tf32 (3xTF32).
// CTA: 256 thr / 8 warps; warp = 16 a-rows x 24 batches (3 n-frags).
// A (W): gmem -> fragment regs, ring prefetch depth 2.
// B (att): staged hi/lo chunks via cp.async double buffer; pitch-24 LDS.
// ---------------------------------------------------------------------------
__global__ __launch_bounds__(256, 4)
void gemm_kernel(const float* __restrict__ W,
                 const float* __restrict__ bias,
                 float* __restrict__ out) {
    int tile = blockIdx.y;
    if (tile >= g_numtiles) return;

    extern __shared__ __align__(16) float bsm[];
    // layout: Bhi[2][KC*BP] at 0, Blo[2][KC*BP] at 2*KC*BP
    float* Bhi = bsm;
    float* Blo = bsm + 2 * KC * BP;

    int tid  = threadIdx.x;
    int w    = tid >> 5, lane = tid & 31;
    int g    = lane >> 2, tig = lane & 3;
    int e    = g_tile_e[tile];
    int mcnt = g_tile_cnt[tile];
    int a0   = blockIdx.x * AB;

    __shared__ int s_bb[MT];
    if (tid < MT) s_bb[tid] = g_perm[g_tile_m0[tile] + min(tid, mcnt - 1)];
    __syncthreads();

    // A row pointers (pre-offset by tig)
    int ra = a0 + w * 16 + g;
    int rb = ra + 8;
    const float* pA0 = W + ((size_t)e * NA + min(ra, NA - 1)) * KDIM + tig;
    const float* pA1 = W + ((size_t)e * NA + min(rb, NA - 1)) * KDIM + tig;

    // B chunk loader: 768 float4 per buffer, 3 per thread (x2 for hi/lo)
    const float* srch = &g_stage_hi[tile][0][0];
    const float* srcl = &g_stage_lo[tile][0][0];
    auto issueB = [&](int c) {
        int buf = c & 1;
        const float* sh_ = srch + c * KC * BP;
        const float* sl_ = srcl + c * KC * BP;
        float* dh = Bhi + buf * KC * BP;
        float* dl = Blo + buf * KC * BP;
        #pragma unroll
        for (int i = 0; i < 3; i++) {
            cp16(dh + (tid + 256 * i) * 4, sh_ + (tid + 256 * i) * 4);
            cp16(dl + (tid + 256 * i) * 4, sl_ + (tid + 256 * i) * 4);
        }
    };
    issueB(0); cp_commit();
    issueB(1); cp_commit();

    // A ring prefetch (raw fp32), depth 2 k8-steps
    float ar[2][4];
    #pragma unroll
    for (int s = 0; s < 2; s++) {
        int k = s * 8;
        ar[s][0] = __ldg(pA0 + k);     ar[s][1] = __ldg(pA1 + k);
        ar[s][2] = __ldg(pA0 + k + 4); ar[s][3] = __ldg(pA1 + k + 4);
    }

    float acc[3][4];
    #pragma unroll
    for (int f = 0; f < 3; f++)
        #pragma unroll
        for (int q = 0; q < 4; q++) acc[f][q] = 0.f;

    for (int c = 0; c < NCH; c++) {
        cp_wait1();
        __syncthreads();
        int buf = c & 1;
        const float* bh = Bhi + buf * KC * BP;
        const float* bl = Blo + buf * KC * BP;

        #pragma unroll 4
        for (int sl = 0; sl < KC / 8; sl++) {
            int s = c * (KC / 8) + sl;
            int slot = s & 1;
            // consume + split
            uint32_t ahi[4], alo[4];
            #pragma unroll
            for (int q = 0; q < 4; q++) {
                float x = ar[slot][q];
                ahi[q] = to_tf32(x);
                alo[q] = to_tf32(x - __uint_as_float(ahi[q]));
            }
            // prefetch s+2 into same slot
            int kp = (s + 2 < 2 * KDIM / 16) ? (s + 2) * 8 : 0;
            ar[slot][0] = __ldg(pA0 + kp);     ar[slot][1] = __ldg(pA1 + kp);
            ar[slot][2] = __ldg(pA0 + kp + 4); ar[slot][3] = __ldg(pA1 + kp + 4);

            int kk = sl * 8;
            #pragma unroll
            for (int f = 0; f < 3; f++) {
                int n = g + 8 * f;
                uint32_t bh0 = __float_as_uint(bh[(kk + tig) * BP + n]);
                uint32_t bh1 = __float_as_uint(bh[(kk + tig + 4) * BP + n]);
                uint32_t bl0 = __float_as_uint(bl[(kk + tig) * BP + n]);
                uint32_t bl1 = __float_as_uint(bl[(kk + tig + 4) * BP + n]);
                mma8(acc[f], ahi, bh0, bh1);
                mma8(acc[f], ahi, bl0, bl1);
                mma8(acc[f], alo, bh0, bh1);
            }
        }
        __syncthreads();
        if (c + 2 < NCH) issueB(c + 2);
        cp_commit();
    }

    // ---- epilogue ----
    float bv0 = (ra < NA) ? bias[e * NA + ra] : 0.f;
    float bv1 = (rb < NA) ? bias[e * NA + rb] : 0.f;
    #pragma unroll
    for (int f = 0; f < 3; f++) {
        int n0 = 8 * f + 2 * tig, n1 = n0 + 1;
        if (n0 < mcnt) {
            if (ra < NA) out[(size_t)s_bb[n0] * NA + ra] = acc[f][0] + bv0;
            if (rb < NA) out[(size_t)s_bb[n0] * NA + rb] = acc[f][2] + bv1;
        }
        if (n1 < mcnt) {
            if (ra < NA) out[(size_t)s_bb[n1] * NA + ra] = acc[f][1] + bv0;
            if (rb < NA) out[(size_t)s_bb[n1] * NA + rb] = acc[f][3] + bv1;
        }
    }
}

// ---------------------------------------------------------------------------
extern "C" void kernel_launch(void* const* d_in, const int* in_sizes, int n_in,
                              void* d_out, int out_size) {
    const float* mask = (const float*)d_in[0];
    const float* feat = (const float*)d_in[1];
    const float* W    = (const float*)d_in[2];
    const float* bias = (const float*)d_in[3];
    const void*  inst = d_in[4];
    float* out = (float*)d_out;

    const int GEMM_SMEM = 4 * KC * BP * 4;   // 49152 B
    cudaFuncSetAttribute(gemm_kernel,
                         cudaFuncAttributeMaxDynamicSharedMemorySize, GEMM_SMEM);

    pool_kernel<<<dim3(BATCH, 8), 256>>>(mask, feat);
    group_kernel<<<1, BATCH>>>(inst);
    stage_kernel<<<dim3(KDIM / KC, MAXTILES), KC>>>();
    gemm_kernel<<<dim3(NABLK, MAXTILES), 256, GEMM_SMEM>>>(W, bias, out);
}

// round 7
// speedup vs baseline: 1.7925x; 1.5747x over previous
#include <cuda_runtime.h>
#include <cstdint>

#define BATCH 256
#define CH    2048
#define HW    196
#define NEXP  16
#define NA    3000
#define KDIM  2048

#define MT       24          // batches per expert tile (N)
#define MAXTILES 32
#define AB       64          // a-rows per CTA (M)
#define NABLK    47          // ceil(3000/64)
#define KC       32          // k-chunk (floats)
#define NCH      (KDIM/KC)   // 64 chunks
#define AP       36          // A smem pitch (bank-conflict-free: 4g+tig)
#define BP       24          // B pitch (conflict-free: 24t mod 32 pattern)

// smem float offsets (2 buffers each)
#define SM_A   0              // [2][64][36] = 4608
#define SM_BH  4608           // [2][768]    = 1536
#define SM_BL  6144           // [2][768]    = 1536
#define SM_TOT 7680           // floats -> 30720 B

__device__ float g_attended[BATCH * CH];
__device__ int   g_perm[BATCH];
__device__ int   g_tile_e[MAXTILES];
__device__ int   g_tile_m0[MAXTILES];
__device__ int   g_tile_cnt[MAXTILES];
__device__ int   g_numtiles;
__device__ __align__(16) float g_stage_hi[MAXTILES][KDIM][BP];
__device__ __align__(16) float g_stage_lo[MAXTILES][KDIM][BP];

// ---------------- helpers ----------------
__device__ __forceinline__ uint32_t to_tf32(float x) {
    uint32_t r;
    asm("cvt.rna.tf32.f32 %0, %1;" : "=r"(r) : "f"(x));
    return r;
}
__device__ __forceinline__ void mma8(float c[4], const uint32_t a[4],
                                     uint32_t b0, uint32_t b1) {
    asm volatile(
        "mma.sync.aligned.m16n8k8.row.col.f32.tf32.tf32.f32 "
        "{%0,%1,%2,%3}, {%4,%5,%6,%7}, {%8,%9}, {%0,%1,%2,%3};"
        : "+f"(c[0]), "+f"(c[1]), "+f"(c[2]), "+f"(c[3])
        : "r"(a[0]), "r"(a[1]), "r"(a[2]), "r"(a[3]), "r"(b0), "r"(b1));
}
__device__ __forceinline__ void cp8(uint32_t sdst, const void* g) {
    asm volatile("cp.async.ca.shared.global [%0], [%1], 8;" :: "r"(sdst), "l"(g));
}
__device__ __forceinline__ void cp_commit() {
    asm volatile("cp.async.commit_group;" ::: "memory");
}
__device__ __forceinline__ void cp_wait1() {
    asm volatile("cp.async.wait_group 1;" ::: "memory");
}

// ---------------------------------------------------------------------------
// Kernel 1: masked weighted average pool (DRAM-bound, at floor).
// ---------------------------------------------------------------------------
__global__ void pool_kernel(const float* __restrict__ mask,
                            const float* __restrict__ feat) {
    int b   = blockIdx.x;
    int tid = threadIdx.x;
    int wid = tid >> 5, lane = tid & 31;

    __shared__ __align__(16) float m_s[HW];
    __shared__ float warp_sum[8];
    __shared__ float s_inv;

    float v = 0.f;
    if (tid < HW) {
        v = mask[b * HW + tid] + 1e-10f;
        m_s[tid] = v;
    }
    #pragma unroll
    for (int o = 16; o > 0; o >>= 1) v += __shfl_down_sync(0xffffffffu, v, o);
    if (lane == 0) warp_sum[wid] = v;
    __syncthreads();
    if (tid == 0) {
        float s = 0.f;
        #pragma unroll
        for (int i = 0; i < 8; i++) s += warp_sum[i];
        s_inv = 1.0f / s;
    }
    __syncthreads();
    float inv = s_inv;

    const float4* m4 = (const float4*)m_s;
    float4 mA = m4[lane];
    float4 mB = (lane < 17) ? m4[lane + 32] : make_float4(0.f, 0.f, 0.f, 0.f);

    int cbase = blockIdx.y * 256 + wid * 32;
    for (int it = 0; it < 32; it++) {
        int c = cbase + it;
        const float4* row = (const float4*)(feat + ((size_t)b * CH + c) * HW);
        float4 f = row[lane];
        float s = f.x * mA.x + f.y * mA.y + f.z * mA.z + f.w * mA.w;
        if (lane < 17) {
            float4 f2 = row[lane + 32];
            s += f2.x * mB.x + f2.y * mB.y + f2.z * mB.z + f2.w * mB.w;
        }
        #pragma unroll
        for (int o = 16; o > 0; o >>= 1) s += __shfl_down_sync(0xffffffffu, s, o);
        if (lane == 0) g_attended[b * CH + c] = s * inv;
    }
}

// ---------------------------------------------------------------------------
// Kernel 2: group batches by expert (stable), tiles of <=24.
// ---------------------------------------------------------------------------
__global__ void group_kernel(const void* __restrict__ inst) {
    int tid = threadIdx.x;
    __shared__ int odd_nz;
    __shared__ int sh_e[BATCH];
    __shared__ int cnt[NEXP];
    __shared__ int off[NEXP + 1];

    if (tid == 0) odd_nz = 0;
    __syncthreads();
    const int* iv = (const int*)inst;
    if (tid < BATCH / 2 && iv[2 * tid + 1] != 0) atomicExch(&odd_nz, 1);
    __syncthreads();

    int e;
    if (odd_nz == 0) e = (int)((const long long*)inst)[tid];
    else             e = iv[tid];

    sh_e[tid] = e;
    if (tid < NEXP) cnt[tid] = 0;
    __syncthreads();

    atomicAdd(&cnt[e], 1);
    int rank = 0;
    for (int j = 0; j < tid; j++) rank += (sh_e[j] == e);
    __syncthreads();

    if (tid == 0) {
        off[0] = 0;
        for (int i = 0; i < NEXP; i++) off[i + 1] = off[i] + cnt[i];
        int nt = 0;
        for (int ei = 0; ei < NEXP; ei++)
            for (int s = 0; s < cnt[ei]; s += MT) {
                g_tile_e[nt]   = ei;
                g_tile_m0[nt]  = off[ei] + s;
                g_tile_cnt[nt] = min(MT, cnt[ei] - s);
                nt++;
            }
        g_numtiles = nt;
    }
    __syncthreads();
    g_perm[off[e] + rank] = tid;
}

// ---------------------------------------------------------------------------
// Kernel 3: stage transposed + tf32 hi/lo split attended panels.
// grid (KDIM/128, MAXTILES) x 128 threads.
// ---------------------------------------------------------------------------
__global__ void stage_kernel() {
    int tile = blockIdx.y;
    if (tile >= g_numtiles) return;
    int k0 = blockIdx.x * 128;
    int tid = threadIdx.x;

    __shared__ float s[MT][128 + 4];
    __shared__ int s_bb[MT];
    if (tid < MT) {
        int m0 = g_tile_m0[tile], mcnt = g_tile_cnt[tile];
        s_bb[tid] = g_perm[m0 + min(tid, mcnt - 1)];
    }
    __syncthreads();

    #pragma unroll
    for (int i = 0; i < 6; i++) {
        int f4 = tid + 128 * i;
        int r = f4 >> 5, c = f4 & 31;
        float4 v = *(const float4*)(g_attended + (size_t)s_bb[r] * KDIM + k0 + c * 4);
        *(float4*)&s[r][c * 4] = v;
    }
    __syncthreads();

    int k = tid;
    float ohi[BP], olo[BP];
    #pragma unroll
    for (int n = 0; n < MT; n++) {
        float x = s[n][k];
        float hi = __uint_as_float(to_tf32(x));
        ohi[n] = hi;
        olo[n] = __uint_as_float(to_tf32(x - hi));
    }
    float* dh = &g_stage_hi[tile][k0 + k][0];
    float* dl = &g_stage_lo[tile][k0 + k][0];
    #pragma unroll
    for (int q = 0; q < BP / 4; q++) {
        *(float4*)(dh + q * 4) = *(float4*)&ohi[q * 4];
        *(float4*)(dl + q * 4) = *(float4*)&olo[q * 4];
    }
}

// ---------------------------------------------------------------------------
// Kernel 4: grouped GEMM via mma.sync tf32 (3xTF32), fully smem-pipelined.
// CTA: 128 thr / 4 warps; warp = 16 a-rows x 24 batches (3 n-frags).
// A (W) and B (att hi/lo) both cp.async double-buffered, KC=32 chunks.
// A smem pitch 36 -> LDS banks 4g+tig (conflict-free).
// ---------------------------------------------------------------------------
__global__ __launch_bounds__(128, 6)
void gemm_kernel(const float* __restrict__ W,
                 const float* __restrict__ bias,
                 float* __restrict__ out) {
    int tile = blockIdx.y;
    if (tile >= g_numtiles) return;

    extern __shared__ __align__(16) float dsm[];
    uint32_t sm_u = (uint32_t)__cvta_generic_to_shared(dsm);

    int tid  = threadIdx.x;
    int w    = tid >> 5, lane = tid & 31;
    int g    = lane >> 2, tig = lane & 3;
    int e    = g_tile_e[tile];
    int mcnt = g_tile_cnt[tile];
    int a0   = blockIdx.x * AB;

    __shared__ int s_bb[MT];
    if (tid < MT) s_bb[tid] = g_perm[g_tile_m0[tile] + min(tid, mcnt - 1)];
    __syncthreads();

    // ---- A loader mapping: thread covers rows r0+8i (i<8), cols cg*2..+1 ----
    int r0 = tid >> 4, cg = tid & 15;
    const char* Wexp = (const char*)(W + (size_t)e * NA * KDIM);
    uint32_t a_off[8];
    #pragma unroll
    for (int i = 0; i < 8; i++)
        a_off[i] = (uint32_t)min(a0 + r0 + 8 * i, NA - 1) * (KDIM * 4) + cg * 8;
    uint32_t adst0 = sm_u + (SM_A + r0 * AP + cg * 2) * 4;

    // ---- B loader mapping: 3 x 8B granules per thread per buffer ----
    const char* bsrcH = (const char*)&g_stage_hi[tile][0][0] + tid * 8;
    const char* bsrcL = (const char*)&g_stage_lo[tile][0][0] + tid * 8;
    uint32_t bdstH = sm_u + (SM_BH + tid * 2) * 4;
    uint32_t bdstL = sm_u + (SM_BL + tid * 2) * 4;

    auto issue = [&](int c) {
        int buf = c & 1;
        const char* wsrc = Wexp + (size_t)c * (KC * 4);
        uint32_t ad = adst0 + buf * (AB * AP * 4);
        #pragma unroll
        for (int i = 0; i < 8; i++)
            cp8(ad + i * (8 * AP * 4), wsrc + a_off[i]);
        const char* bh = bsrcH + (size_t)c * (KC * BP * 4);
        const char* bl = bsrcL + (size_t)c * (KC * BP * 4);
        uint32_t dh = bdstH + buf * (KC * BP * 4);
        uint32_t dl = bdstL + buf * (KC * BP * 4);
        #pragma unroll
        for (int j = 0; j < 3; j++) {
            cp8(dh + j * 1024, bh + j * 1024);
            cp8(dl + j * 1024, bl + j * 1024);
        }
    };

    issue(0); cp_commit();
    issue(1); cp_commit();

    float acc[3][4];
    #pragma unroll
    for (int f = 0; f < 3; f++)
        #pragma unroll
        for (int q = 0; q < 4; q++) acc[f][q] = 0.f;

    for (int c = 0; c < NCH; c++) {
        cp_wait1();
        __syncthreads();
        int buf = c & 1;
        const float* As = dsm + SM_A + buf * (AB * AP) + w * 16 * AP;
        const float* Bh = dsm + SM_BH + buf * (KC * BP);
        const float* Bl = dsm + SM_BL + buf * (KC * BP);

        #pragma unroll
        for (int sl = 0; sl < KC / 8; sl++) {
            int kk = sl * 8;
            float a0f = As[g * AP + kk + tig];
            float a1f = As[(g + 8) * AP + kk + tig];
            float a2f = As[g * AP + kk + tig + 4];
            float a3f = As[(g + 8) * AP + kk + tig + 4];
            uint32_t ahi[4], alo[4];
            ahi[0] = to_tf32(a0f); alo[0] = to_tf32(a0f - __uint_as_float(ahi[0]));
            ahi[1] = to_tf32(a1f); alo[1] = to_tf32(a1f - __uint_as_float(ahi[1]));
            ahi[2] = to_tf32(a2f); alo[2] = to_tf32(a2f - __uint_as_float(ahi[2]));
            ahi[3] = to_tf32(a3f); alo[3] = to_tf32(a3f - __uint_as_float(ahi[3]));

            #pragma unroll
            for (int f = 0; f < 3; f++) {
                int n = g + 8 * f;
                uint32_t bh0 = __float_as_uint(Bh[(kk + tig) * BP + n]);
                uint32_t bh1 = __float_as_uint(Bh[(kk + tig + 4) * BP + n]);
                uint32_t bl0 = __float_as_uint(Bl[(kk + tig) * BP + n]);
                uint32_t bl1 = __float_as_uint(Bl[(kk + tig + 4) * BP + n]);
                mma8(acc[f], ahi, bh0, bh1);
                mma8(acc[f], ahi, bl0, bl1);
                mma8(acc[f], alo, bh0, bh1);
            }
        }
        __syncthreads();
        if (c + 2 < NCH) issue(c + 2);
        cp_commit();
    }

    // ---- epilogue ----
    int ra = a0 + w * 16 + g;
    int rb = ra + 8;
    float bv0 = (ra < NA) ? bias[e * NA + ra] : 0.f;
    float bv1 = (rb < NA) ? bias[e * NA + rb] : 0.f;
    #pragma unroll
    for (int f = 0; f < 3; f++) {
        int n0 = 8 * f + 2 * tig, n1 = n0 + 1;
        if (n0 < mcnt) {
            if (ra < NA) out[(size_t)s_bb[n0] * NA + ra] = acc[f][0] + bv0;
            if (rb < NA) out[(size_t)s_bb[n0] * NA + rb] = acc[f][2] + bv1;
        }
        if (n1 < mcnt) {
            if (ra < NA) out[(size_t)s_bb[n1] * NA + ra] = acc[f][1] + bv0;
            if (rb < NA) out[(size_t)s_bb[n1] * NA + rb] = acc[f][3] + bv1;
        }
    }
}

// ---------------------------------------------------------------------------
extern "C" void kernel_launch(void* const* d_in, const int* in_sizes, int n_in,
                              void* d_out, int out_size) {
    const float* mask = (const float*)d_in[0];
    const float* feat = (const float*)d_in[1];
    const float* W    = (const float*)d_in[2];
    const float* bias = (const float*)d_in[3];
    const void*  inst = d_in[4];
    float* out = (float*)d_out;

    const int GEMM_SMEM = SM_TOT * 4;   // 30720 B
    cudaFuncSetAttribute(gemm_kernel,
                         cudaFuncAttributeMaxDynamicSharedMemorySize, GEMM_SMEM);

    pool_kernel<<<dim3(BATCH, 8), 256>>>(mask, feat);
    group_kernel<<<1, BATCH>>>(inst);
    stage_kernel<<<dim3(KDIM / 128, MAXTILES), 128>>>();
    gemm_kernel<<<dim3(NABLK, MAXTILES), 128, GEMM_SMEM>>>(W, bias, out);
}

// round 8
// speedup vs baseline: 1.9086x; 1.0648x over previous
#include <cuda_runtime.h>
#include <cstdint>

#define BATCH 256
#define CH    2048
#define HW    196
#define NEXP  16
#define NA    3000
#define KDIM  2048

#define MT       24          // batches per expert tile (N)
#define MAXTILES 32
#define AB       64          // a-rows per CTA (M)
#define NABLK    47          // ceil(3000/64)
#define KC       32          // k-chunk (floats)
#define NCH      (KDIM/KC)   // 64 chunks
#define AP       36          // A smem pitch (floats)
#define BPF2     28          // B pitch in float2 per (sl,tig) row
#define BCHUNK   (16*2*BPF2) // 896 floats per chunk per (hi|lo)

// smem float offsets
#define SM_A   0                 // [2][64][36]  = 4608
#define SM_BH  4608              // [2][896]     = 1792
#define SM_BL  6400              // [2][896]     = 1792
#define SM_TOT 8192              // floats -> 32768 B

__device__ float g_attended[BATCH * CH];
__device__ int   g_perm[BATCH];
__device__ int   g_tile_e[MAXTILES];
__device__ int   g_tile_m0[MAXTILES];
__device__ int   g_tile_cnt[MAXTILES];
__device__ int   g_numtiles;
// staged B panels: [tile][chunk][ (sl*4+tig)*56 + 2n + h ]
__device__ __align__(16) float g_stage_hi[MAXTILES][NCH][BCHUNK];
__device__ __align__(16) float g_stage_lo[MAXTILES][NCH][BCHUNK];

// ---------------- helpers ----------------
__device__ __forceinline__ uint32_t to_tf32(float x) {
    uint32_t r;
    asm("cvt.rna.tf32.f32 %0, %1;" : "=r"(r) : "f"(x));
    return r;
}
__device__ __forceinline__ void mma8(float c[4], const uint32_t a[4],
                                     uint32_t b0, uint32_t b1) {
    asm volatile(
        "mma.sync.aligned.m16n8k8.row.col.f32.tf32.tf32.f32 "
        "{%0,%1,%2,%3}, {%4,%5,%6,%7}, {%8,%9}, {%0,%1,%2,%3};"
        : "+f"(c[0]), "+f"(c[1]), "+f"(c[2]), "+f"(c[3])
        : "r"(a[0]), "r"(a[1]), "r"(a[2]), "r"(a[3]), "r"(b0), "r"(b1));
}
__device__ __forceinline__ void cp16(uint32_t sdst, const void* g) {
    asm volatile("cp.async.cg.shared.global [%0], [%1], 16;" :: "r"(sdst), "l"(g));
}
__device__ __forceinline__ void cp_commit() {
    asm volatile("cp.async.commit_group;" ::: "memory");
}
__device__ __forceinline__ void cp_wait1() {
    asm volatile("cp.async.wait_group 1;" ::: "memory");
}

// ---------------------------------------------------------------------------
// Kernel 1: masked weighted average pool (DRAM-bound, at floor).
// ---------------------------------------------------------------------------
__global__ void pool_kernel(const float* __restrict__ mask,
                            const float* __restrict__ feat) {
    int b   = blockIdx.x;
    int tid = threadIdx.x;
    int wid = tid >> 5, lane = tid & 31;

    __shared__ __align__(16) float m_s[HW];
    __shared__ float warp_sum[8];
    __shared__ float s_inv;

    float v = 0.f;
    if (tid < HW) {
        v = mask[b * HW + tid] + 1e-10f;
        m_s[tid] = v;
    }
    #pragma unroll
    for (int o = 16; o > 0; o >>= 1) v += __shfl_down_sync(0xffffffffu, v, o);
    if (lane == 0) warp_sum[wid] = v;
    __syncthreads();
    if (tid == 0) {
        float s = 0.f;
        #pragma unroll
        for (int i = 0; i < 8; i++) s += warp_sum[i];
        s_inv = 1.0f / s;
    }
    __syncthreads();
    float inv = s_inv;

    const float4* m4 = (const float4*)m_s;
    float4 mA = m4[lane];
    float4 mB = (lane < 17) ? m4[lane + 32] : make_float4(0.f, 0.f, 0.f, 0.f);

    int cbase = blockIdx.y * 256 + wid * 32;
    for (int it = 0; it < 32; it++) {
        int c = cbase + it;
        const float4* row = (const float4*)(feat + ((size_t)b * CH + c) * HW);
        float4 f = row[lane];
        float s = f.x * mA.x + f.y * mA.y + f.z * mA.z + f.w * mA.w;
        if (lane < 17) {
            float4 f2 = row[lane + 32];
            s += f2.x * mB.x + f2.y * mB.y + f2.z * mB.z + f2.w * mB.w;
        }
        #pragma unroll
        for (int o = 16; o > 0; o >>= 1) s += __shfl_down_sync(0xffffffffu, s, o);
        if (lane == 0) g_attended[b * CH + c] = s * inv;
    }
}

// ---------------------------------------------------------------------------
// Kernel 2: group batches by expert (stable), tiles of <=24.
// ---------------------------------------------------------------------------
__global__ void group_kernel(const void* __restrict__ inst) {
    int tid = threadIdx.x;
    __shared__ int odd_nz;
    __shared__ int sh_e[BATCH];
    __shared__ int cnt[NEXP];
    __shared__ int off[NEXP + 1];

    if (tid == 0) odd_nz = 0;
    __syncthreads();
    const int* iv = (const int*)inst;
    if (tid < BATCH / 2 && iv[2 * tid + 1] != 0) atomicExch(&odd_nz, 1);
    __syncthreads();

    int e;
    if (odd_nz == 0) e = (int)((const long long*)inst)[tid];
    else             e = iv[tid];

    sh_e[tid] = e;
    if (tid < NEXP) cnt[tid] = 0;
    __syncthreads();

    atomicAdd(&cnt[e], 1);
    int rank = 0;
    for (int j = 0; j < tid; j++) rank += (sh_e[j] == e);
    __syncthreads();

    if (tid == 0) {
        off[0] = 0;
        for (int i = 0; i < NEXP; i++) off[i + 1] = off[i] + cnt[i];
        int nt = 0;
        for (int ei = 0; ei < NEXP; ei++)
            for (int s = 0; s < cnt[ei]; s += MT) {
                g_tile_e[nt]   = ei;
                g_tile_m0[nt]  = off[ei] + s;
                g_tile_cnt[nt] = min(MT, cnt[ei] - s);
                nt++;
            }
        g_numtiles = nt;
    }
    __syncthreads();
    g_perm[off[e] + rank] = tid;
}

// ---------------------------------------------------------------------------
// Kernel 3: stage k-pair-packed tf32 hi/lo B panels.
//   element [tile][c][(sl*4+tig)*56 + 2n + h] = tf32_part(att[bb[n]][k])
//   with k = c*32 + sl*8 + tig + 4h.
// grid (KDIM/128, MAXTILES) x 128 threads (block covers 4 chunks).
// ---------------------------------------------------------------------------
__global__ void stage_kernel() {
    int tile = blockIdx.y;
    if (tile >= g_numtiles) return;
    int k0 = blockIdx.x * 128;
    int tid = threadIdx.x;

    __shared__ float s[MT][128 + 4];
    __shared__ int s_bb[MT];
    if (tid < MT) {
        int m0 = g_tile_m0[tile], mcnt = g_tile_cnt[tile];
        s_bb[tid] = g_perm[m0 + min(tid, mcnt - 1)];
    }
    __syncthreads();

    #pragma unroll
    for (int i = 0; i < 6; i++) {
        int f4 = tid + 128 * i;
        int r = f4 >> 5, c = f4 & 31;
        float4 v = *(const float4*)(g_attended + (size_t)s_bb[r] * KDIM + k0 + c * 4);
        *(float4*)&s[r][c * 4] = v;
    }
    __syncthreads();

    // thread (p, half): p = k-pair slot, half selects n range
    int p = tid & 63, half = tid >> 6;
    int cc = p >> 4, sl = (p >> 2) & 3, tig = p & 3;
    int kl = cc * 32 + sl * 8 + tig;
    int c  = blockIdx.x * 4 + cc;
    float* dh = &g_stage_hi[tile][c][(sl * 4 + tig) * (2 * BPF2)];
    float* dl = &g_stage_lo[tile][c][(sl * 4 + tig) * (2 * BPF2)];

    #pragma unroll
    for (int i = 0; i < 12; i++) {
        int n = half * 12 + i;
        float x0 = s[n][kl], x1 = s[n][kl + 4];
        float h0 = __uint_as_float(to_tf32(x0));
        float h1 = __uint_as_float(to_tf32(x1));
        float l0 = __uint_as_float(to_tf32(x0 - h0));
        float l1 = __uint_as_float(to_tf32(x1 - h1));
        *(float2*)(dh + 2 * n) = make_float2(h0, h1);
        *(float2*)(dl + 2 * n) = make_float2(l0, l1);
    }
}

// ---------------------------------------------------------------------------
// Kernel 4: grouped GEMM via mma.sync tf32 (3xTF32), smem-pipelined.
// CTA: 128 thr / 4 warps; warp = 16 a-rows x (nf*8) batches.
// nf = ceil(mcnt/8): padding n-frags are skipped entirely.
// B: k-pair float2 layout, 2 LDS.64 per frag; MMAs issued term-major.
// ---------------------------------------------------------------------------
__global__ __launch_bounds__(128, 6)
void gemm_kernel(const float* __restrict__ W,
                 const float* __restrict__ bias,
                 float* __restrict__ out) {
    int tile = blockIdx.y;
    if (tile >= g_numtiles) return;

    extern __shared__ __align__(16) float dsm[];
    uint32_t sm_u = (uint32_t)__cvta_generic_to_shared(dsm);

    int tid  = threadIdx.x;
    int w    = tid >> 5, lane = tid & 31;
    int g    = lane >> 2, tig = lane & 3;
    int e    = g_tile_e[tile];
    int mcnt = g_tile_cnt[tile];
    int nf   = (mcnt + 7) >> 3;
    int a0   = blockIdx.x * AB;

    __shared__ int s_bb[MT];
    if (tid < MT) s_bb[tid] = g_perm[g_tile_m0[tile] + min(tid, mcnt - 1)];
    __syncthreads();

    // ---- A loader: 4 cp16 per thread, rows r0+16j, col-quad c4 ----
    int r0 = tid >> 3, c4 = tid & 7;
    const char* Wexp = (const char*)(W + (size_t)e * NA * KDIM);
    uint32_t a_off[4];
    #pragma unroll
    for (int j = 0; j < 4; j++)
        a_off[j] = (uint32_t)min(a0 + r0 + 16 * j, NA - 1) * (KDIM * 4) + c4 * 16;
    uint32_t adst0 = sm_u + (SM_A + r0 * AP + c4 * 4) * 4;

    const char* bsrcH = (const char*)&g_stage_hi[tile][0][0];
    const char* bsrcL = (const char*)&g_stage_lo[tile][0][0];

    auto issue = [&](int c) {
        int buf = c & 1;
        const char* wsrc = Wexp + (size_t)c * (KC * 4);
        uint32_t ad = adst0 + buf * (AB * AP * 4);
        #pragma unroll
        for (int j = 0; j < 4; j++)
            cp16(ad + j * (16 * AP * 4), wsrc + a_off[j]);
        // B: 224 f4 per (hi|lo) buffer
        const char* bh = bsrcH + (size_t)c * (BCHUNK * 4);
        const char* bl = bsrcL + (size_t)c * (BCHUNK * 4);
        uint32_t dh = sm_u + (SM_BH + buf * BCHUNK) * 4;
        uint32_t dl = sm_u + (SM_BL + buf * BCHUNK) * 4;
        cp16(dh + tid * 16, bh + tid * 16);
        cp16(dl + tid * 16, bl + tid * 16);
        if (tid < 96) {
            cp16(dh + 2048 + tid * 16, bh + 2048 + tid * 16);
            cp16(dl + 2048 + tid * 16, bl + 2048 + tid * 16);
        }
    };

    issue(0); cp_commit();
    issue(1); cp_commit();

    float acc[3][4];
    #pragma unroll
    for (int f = 0; f < 3; f++)
        #pragma unroll
        for (int q = 0; q < 4; q++) acc[f][q] = 0.f;

    for (int c = 0; c < NCH; c++) {
        cp_wait1();
        __syncthreads();
        int buf = c & 1;
        const float* As = dsm + SM_A + buf * (AB * AP) + w * 16 * AP;
        const float* Bh = dsm + SM_BH + buf * BCHUNK;
        const float* Bl = dsm + SM_BL + buf * BCHUNK;

        #pragma unroll
        for (int sl = 0; sl < KC / 8; sl++) {
            int kk = sl * 8;
            float a0f = As[g * AP + kk + tig];
            float a1f = As[(g + 8) * AP + kk + tig];
            float a2f = As[g * AP + kk + tig + 4];
            float a3f = As[(g + 8) * AP + kk + tig + 4];
            uint32_t ahi[4], alo[4];
            ahi[0] = to_tf32(a0f); alo[0] = to_tf32(a0f - __uint_as_float(ahi[0]));
            ahi[1] = to_tf32(a1f); alo[1] = to_tf32(a1f - __uint_as_float(ahi[1]));
            ahi[2] = to_tf32(a2f); alo[2] = to_tf32(a2f - __uint_as_float(ahi[2]));
            ahi[3] = to_tf32(a3f); alo[3] = to_tf32(a3f - __uint_as_float(ahi[3]));

            int bbase = (sl * 4 + tig) * (2 * BPF2) + 2 * g;
            float2 bh2[3], bl2[3];
            #pragma unroll
            for (int f = 0; f < 3; f++)
                if (f < nf) {
                    bh2[f] = *(const float2*)(Bh + bbase + 16 * f);
                    bl2[f] = *(const float2*)(Bl + bbase + 16 * f);
                }
            // term-major MMA issue: spaces same-acc writes nf apart
            #pragma unroll
            for (int f = 0; f < 3; f++)
                if (f < nf)
                    mma8(acc[f], ahi, __float_as_uint(bh2[f].x),
                                      __float_as_uint(bh2[f].y));
            #pragma unroll
            for (int f = 0; f < 3; f++)
                if (f < nf)
                    mma8(acc[f], ahi, __float_as_uint(bl2[f].x),
                                      __float_as_uint(bl2[f].y));
            #pragma unroll
            for (int f = 0; f < 3; f++)
                if (f < nf)
                    mma8(acc[f], alo, __float_as_uint(bh2[f].x),
                                      __float_as_uint(bh2[f].y));
        }
        __syncthreads();
        if (c + 2 < NCH) issue(c + 2);
        cp_commit();
    }

    // ---- epilogue ----
    int ra = a0 + w * 16 + g;
    int rb = ra + 8;
    float bv0 = (ra < NA) ? bias[e * NA + ra] : 0.f;
    float bv1 = (rb < NA) ? bias[e * NA + rb] : 0.f;
    #pragma unroll
    for (int f = 0; f < 3; f++) {
        int n0 = 8 * f + 2 * tig, n1 = n0 + 1;
        if (n0 < mcnt) {
            if (ra < NA) out[(size_t)s_bb[n0] * NA + ra] = acc[f][0] + bv0;
            if (rb < NA) out[(size_t)s_bb[n0] * NA + rb] = acc[f][2] + bv1;
        }
        if (n1 < mcnt) {
            if (ra < NA) out[(size_t)s_bb[n1] * NA + ra] = acc[f][1] + bv0;
            if (rb < NA) out[(size_t)s_bb[n1] * NA + rb] = acc[f][3] + bv1;
        }
    }
}

// ---------------------------------------------------------------------------
extern "C" void kernel_launch(void* const* d_in, const int* in_sizes, int n_in,
                              void* d_out, int out_size) {
    const float* mask = (const float*)d_in[0];
    const float* feat = (const float*)d_in[1];
    const float* W    = (const float*)d_in[2];
    const float* bias = (const float*)d_in[3];
    const void*  inst = d_in[4];
    float* out = (float*)d_out;

    const int GEMM_SMEM = SM_TOT * 4;   // 32768 B
    cudaFuncSetAttribute(gemm_kernel,
                         cudaFuncAttributeMaxDynamicSharedMemorySize, GEMM_SMEM);

    pool_kernel<<<dim3(BATCH, 8), 256>>>(mask, feat);
    group_kernel<<<1, BATCH>>>(inst);
    stage_kernel<<<dim3(KDIM / 128, MAXTILES), 128>>>();
    gemm_kernel<<<dim3(NABLK, MAXTILES), 128, GEMM_SMEM>>>(W, bias, out);
}